// round 12
// baseline (speedup 1.0000x reference)
#include <cuda_runtime.h>
#include <cuda_fp16.h>

#define NROWS   16384
#define INC     512
#define NG      64
#define NF      24
#define NO      16
#define ACCC    3584
#define RT      16
#define NTHR    256
#define TILE_BYTES (ACCC * RT * 2)   // 114688 (fp16 tile)
#define SMEM_ASK   122880            // pad: forces 1 block/SM, leaves ~108KB L1

typedef unsigned long long u64;

static __device__ __forceinline__ u64 pk2(float a, float b) {
    u64 r;
    asm("mov.b64 %0, {%1, %2};" : "=l"(r) : "f"(a), "f"(b));
    return r;
}
static __device__ __forceinline__ void up2(u64 v, float &a, float &b) {
    asm("mov.b64 {%0, %1}, %2;" : "=f"(a), "=f"(b) : "l"(v));
}
static __device__ __forceinline__ u64 fma2(u64 a, u64 b, u64 c) {
    u64 d;
    asm("fma.rn.f32x2 %0, %1, %2, %3;" : "=l"(d) : "l"(a), "l"(b), "l"(c));
    return d;
}
static __device__ __forceinline__ float tanhhw(float x) {
    float y;
    asm("tanh.approx.f32 %0, %1;" : "=f"(y) : "f"(x));
    return y;
}
static __device__ __forceinline__ float2 h2f(unsigned u) {
    __half2 h = reinterpret_cast<__half2&>(u);
    return __half22float2(h);
}

// fp16 tile [col][16 rows]: column = 32 B = 4 slots of 8 B (4 rows each).
// Slot s of column c lives at physical slot s ^ H2(c).
// H2 mixes col bits 2..5: spreads banks for random gathers, the staging
// stores (consecutive c across lanes) and the writeback (c differs by 16).
#define H2(c)  ((((c) >> 2) ^ ((c) >> 4)) & 3)

static __device__ __forceinline__ uint2* qp(uint2* tile, int c, int s) {
    return tile + c * 4 + (s ^ H2(c));
}

// Thread = (g, s): group g, row-quad s (rows 4s..4s+3), all 16 outputs.
// acc[r][op] = f32x2 over outputs (2op, 2op+1) for local row r.
// Depth-2 rolling weight prefetch (full 64B row, 3 buffers).
static __device__ __forceinline__ void glayer(uint2* tile, int g, int s,
                                              const float* __restrict__ W,
                                              const float* __restrict__ bia,
                                              const int* __restrict__ idx,
                                              int colbase)
{
    int cols[NF];
    const int4* ip = reinterpret_cast<const int4*>(idx + g * NF);
    #pragma unroll
    for (int i = 0; i < NF / 4; i++) {
        int4 v = __ldg(&ip[i]);
        cols[4 * i + 0] = v.x; cols[4 * i + 1] = v.y;
        cols[4 * i + 2] = v.z; cols[4 * i + 3] = v.w;
    }
    const ulonglong2* wb = reinterpret_cast<const ulonglong2*>(W + (size_t)g * NF * NO);
    const float2*     b2 = reinterpret_cast<const float2*>(bia + g * NO);

    u64 acc[4][8];
    #pragma unroll
    for (int op = 0; op < 8; op++) {
        float2 bb = __ldg(&b2[op]);
        u64 bv = pk2(bb.x, bb.y);
        acc[0][op] = bv; acc[1][op] = bv; acc[2][op] = bv; acc[3][op] = bv;
    }

    // depth-2 rolling prefetch of the whole 64B weight row (4x ulonglong2)
    ulonglong2 w0[3], w1[3], w2[3], w3[3];
    #pragma unroll
    for (int d = 0; d < 2; d++) {
        w0[d] = __ldg(&wb[d * 4 + 0]);
        w1[d] = __ldg(&wb[d * 4 + 1]);
        w2[d] = __ldg(&wb[d * 4 + 2]);
        w3[d] = __ldg(&wb[d * 4 + 3]);
    }

    #pragma unroll
    for (int f = 0; f < NF; f++) {
        if (f + 2 < NF) {
            int b = (f + 2) % 3;
            w0[b] = __ldg(&wb[(f + 2) * 4 + 0]);
            w1[b] = __ldg(&wb[(f + 2) * 4 + 1]);
            w2[b] = __ldg(&wb[(f + 2) * 4 + 2]);
            w3[b] = __ldg(&wb[(f + 2) * 4 + 3]);
        }
        int c = cols[f];
        uint2 a = *qp(tile, c, s);
        float2 r01 = h2f(a.x), r23 = h2f(a.y);
        u64 d0 = pk2(r01.x, r01.x), d1 = pk2(r01.y, r01.y);
        u64 d2 = pk2(r23.x, r23.x), d3 = pk2(r23.y, r23.y);
        int bi = f % 3;
        u64 u[8] = {w0[bi].x, w0[bi].y, w1[bi].x, w1[bi].y,
                    w2[bi].x, w2[bi].y, w3[bi].x, w3[bi].y};
        #pragma unroll
        for (int op = 0; op < 8; op++) {
            acc[0][op] = fma2(d0, u[op], acc[0][op]);
            acc[1][op] = fma2(d1, u[op], acc[1][op]);
            acc[2][op] = fma2(d2, u[op], acc[2][op]);
            acc[3][op] = fma2(d3, u[op], acc[3][op]);
        }
    }

    // tanh + fp16 writeback: 16 cols x 4 rows
    float v[4][NO];
    #pragma unroll
    for (int r = 0; r < 4; r++)
        #pragma unroll
        for (int op = 0; op < 8; op++)
            up2(acc[r][op], v[r][2 * op], v[r][2 * op + 1]);
    #pragma unroll
    for (int r = 0; r < 4; r++)
        #pragma unroll
        for (int o = 0; o < NO; o++)
            v[r][o] = tanhhw(v[r][o]);
    #pragma unroll
    for (int o = 0; o < NO; o++) {
        int c = colbase + g * NO + o;
        __half2 p0 = __floats2half2_rn(v[0][o], v[1][o]);
        __half2 p1 = __floats2half2_rn(v[2][o], v[3][o]);
        uint2 st;
        st.x = reinterpret_cast<unsigned&>(p0);
        st.y = reinterpret_cast<unsigned&>(p1);
        *qp(tile, c, s) = st;
    }
}

__global__ void __launch_bounds__(NTHR, 1)
model_kernel(const float* __restrict__ x,
             const float* __restrict__ W1, const float* __restrict__ b1,
             const float* __restrict__ W2, const float* __restrict__ b2,
             const float* __restrict__ W3, const float* __restrict__ b3,
             const float* __restrict__ Wo, const float* __restrict__ bo,
             const int* __restrict__ idx1, const int* __restrict__ idx2,
             const int* __restrict__ idx3, const int* __restrict__ idxo,
             float* __restrict__ out)
{
    extern __shared__ uint2 tile[];  // [ACCC][4 slots] fp16, slot-hash swizzle
    const int t = threadIdx.x;
    const int rowbase = blockIdx.x * RT;

    // ---- Stage x tile (16 rows x 512 cols) fp32->fp16 into SMEM ----
    // item = (slot qd, col c): 4 streaming LDG.32 (evict-first: don't thrash
    // the L1-resident weights), one STS.64 hash-spread.
    {
        const float* xb = x + (size_t)rowbase * INC;
        #pragma unroll
        for (int k = 0; k < 8; k++) {
            int i  = t + k * NTHR;       // 0..2047
            int c  = i & 511;
            int qd = i >> 9;             // 0..3
            float r0 = __ldcs(&xb[(4 * qd + 0) * INC + c]);
            float r1 = __ldcs(&xb[(4 * qd + 1) * INC + c]);
            float r2 = __ldcs(&xb[(4 * qd + 2) * INC + c]);
            float r3 = __ldcs(&xb[(4 * qd + 3) * INC + c]);
            __half2 p0 = __floats2half2_rn(r0, r1);
            __half2 p1 = __floats2half2_rn(r2, r3);
            uint2 st;
            st.x = reinterpret_cast<unsigned&>(p0);
            st.y = reinterpret_cast<unsigned&>(p1);
            *qp(tile, c, qd) = st;
        }
    }
    __syncthreads();

    const int g = t >> 2;   // group 0..63
    const int s = t & 3;    // row-quad 0..3

    glayer(tile, g, s, W1, b1, idx1, 512);
    __syncthreads();
    glayer(tile, g, s, W2, b2, idx2, 1536);
    __syncthreads();
    glayer(tile, g, s, W3, b3, idx3, 2560);
    __syncthreads();

    // ---- Output layer: 4 groups x 48 f x 16 o, linear, fp32 out ----
    // thread = (ot, og, so): output col ot of group og, rows 4so..4so+3.
    {
        int ot = t & 15;
        int og = (t >> 4) & 3;
        int so = t >> 6;                 // 0..3
        float bias = __ldg(&bo[og * 16 + ot]);
        u64 bd = pk2(bias, bias);
        u64 h01 = bd, h23 = bd;
        const int* gi = idxo + og * 48;
        const float* w = Wo + og * 48 * 16 + ot;
        #pragma unroll
        for (int f = 0; f < 48; f++) {
            int c = __ldg(&gi[f]);
            uint2 a = *qp(tile, c, so);
            float2 r01 = h2f(a.x), r23 = h2f(a.y);
            float wf = __ldg(&w[f * 16]);
            u64 wd = pk2(wf, wf);
            h01 = fma2(pk2(r01.x, r01.y), wd, h01);
            h23 = fma2(pk2(r23.x, r23.y), wd, h23);
        }
        float hv[4];
        up2(h01, hv[0], hv[1]);
        up2(h23, hv[2], hv[3]);
        float* ob = out + (size_t)(rowbase + 4 * so) * 64 + og * 16 + ot;
        ob[0]   = hv[0];
        ob[64]  = hv[1];
        ob[128] = hv[2];
        ob[192] = hv[3];
    }
}

extern "C" void kernel_launch(void* const* d_in, const int* in_sizes, int n_in,
                              void* d_out, int out_size)
{
    const float* x   = (const float*)d_in[0];
    const float* W1  = (const float*)d_in[1];
    const float* b1  = (const float*)d_in[2];
    const float* W2  = (const float*)d_in[3];
    const float* b2  = (const float*)d_in[4];
    const float* W3  = (const float*)d_in[5];
    const float* b3  = (const float*)d_in[6];
    const float* Wo  = (const float*)d_in[7];
    const float* bo  = (const float*)d_in[8];
    const int*   i1  = (const int*)d_in[9];
    const int*   i2  = (const int*)d_in[10];
    const int*   i3  = (const int*)d_in[11];
    const int*   io  = (const int*)d_in[12];
    float*       out = (float*)d_out;

    cudaFuncSetAttribute(model_kernel,
                         cudaFuncAttributeMaxDynamicSharedMemorySize, SMEM_ASK);
    model_kernel<<<NROWS / RT, NTHR, SMEM_ASK>>>(
        x, W1, b1, W2, b2, W3, b3, Wo, bo, i1, i2, i3, io, out);
}

// round 13
// speedup vs baseline: 1.0670x; 1.0670x over previous
#include <cuda_runtime.h>
#include <cuda_fp16.h>

#define NROWS   16384
#define INC     512
#define NG      64
#define NF      24
#define NO      16
#define ACCC    3584
#define RT      16
#define NTHR    256
#define TILE_BYTES (ACCC * RT * 2)       // 114688 (fp16 tile)
#define WPAD    388                       // padded words per group (384+4)
#define WSM_BYTES (NG * WPAD * 4)         // 99328
#define SMEM_ASK  (TILE_BYTES + WSM_BYTES)  // 214016

typedef unsigned long long u64;

static __device__ __forceinline__ u64 pk2(float a, float b) {
    u64 r;
    asm("mov.b64 %0, {%1, %2};" : "=l"(r) : "f"(a), "f"(b));
    return r;
}
static __device__ __forceinline__ void up2(u64 v, float &a, float &b) {
    asm("mov.b64 {%0, %1}, %2;" : "=f"(a), "=f"(b) : "l"(v));
}
static __device__ __forceinline__ u64 fma2(u64 a, u64 b, u64 c) {
    u64 d;
    asm("fma.rn.f32x2 %0, %1, %2, %3;" : "=l"(d) : "l"(a), "l"(b), "l"(c));
    return d;
}
static __device__ __forceinline__ float tanhhw(float x) {
    float y;
    asm("tanh.approx.f32 %0, %1;" : "=f"(y) : "f"(x));
    return y;
}
static __device__ __forceinline__ float2 h2f(unsigned u) {
    __half2 h = reinterpret_cast<__half2&>(u);
    return __half22float2(h);
}

// fp16 tile [col][16 rows]: column = 32 B = 4 slots of 8 B (4 rows each).
// Slot s of column c lives at physical slot s ^ H2(c); H2 mixes col bits
// 2..5 so random gathers, staging stores and the 16-col writeback all spread.
#define H2(c)  ((((c) >> 2) ^ ((c) >> 4)) & 3)

static __device__ __forceinline__ uint2* qp(uint2* tile, int c, int s) {
    return tile + c * 4 + (s ^ H2(c));
}

// Cooperative copy of one layer's weights W[64][24][16] fp32 into SMEM with
// group stride padded to WPAD words (bank-spreads the 8 groups of a warp).
static __device__ __forceinline__ void stageW(const float* __restrict__ W,
                                              float* wsm, int t)
{
    const float4* src = reinterpret_cast<const float4*>(W);
    float4* dst = reinterpret_cast<float4*>(wsm);
    #pragma unroll
    for (int it = 0; it < 24; it++) {
        int i   = t + it * NTHR;       // 0..6143, fully coalesced LDG.128
        int row = i >> 2;              // (g,f) row 0..1535
        int k   = i & 3;
        int g   = row / NF;
        int f   = row - g * NF;
        dst[g * (WPAD / 4) + f * 4 + k] = __ldg(&src[i]);
    }
}

// Thread = (g, s): group g, row-quad s (rows 4s..4s+3), all 16 outputs.
// Weights read from SMEM (broadcast across the 4 s-threads of a group),
// depth-1 rolling prefetch of weights + activation.
static __device__ __forceinline__ void glayer(uint2* tile,
                                              const float* wsm,
                                              int g, int s,
                                              const float* __restrict__ bia,
                                              const int* __restrict__ idx,
                                              int colbase)
{
    int cols[NF];
    const int4* ip = reinterpret_cast<const int4*>(idx + g * NF);
    #pragma unroll
    for (int i = 0; i < NF / 4; i++) {
        int4 v = __ldg(&ip[i]);
        cols[4 * i + 0] = v.x; cols[4 * i + 1] = v.y;
        cols[4 * i + 2] = v.z; cols[4 * i + 3] = v.w;
    }

    u64 acc[4][8];
    {
        const float2* b2 = reinterpret_cast<const float2*>(bia + g * NO);
        #pragma unroll
        for (int op = 0; op < 8; op++) {
            float2 bb = __ldg(&b2[op]);
            u64 bv = pk2(bb.x, bb.y);
            acc[0][op] = bv; acc[1][op] = bv; acc[2][op] = bv; acc[3][op] = bv;
        }
    }

    const ulonglong2* wg = reinterpret_cast<const ulonglong2*>(wsm + g * WPAD);

    // depth-1 prefetch (f = 0 primed)
    ulonglong2 cw0 = wg[0], cw1 = wg[1], cw2 = wg[2], cw3 = wg[3];
    uint2 ca = *qp(tile, cols[0], s);

    #pragma unroll
    for (int f = 0; f < NF; f++) {
        ulonglong2 nw0, nw1, nw2, nw3;
        uint2 na;
        if (f < NF - 1) {
            nw0 = wg[(f + 1) * 4 + 0];
            nw1 = wg[(f + 1) * 4 + 1];
            nw2 = wg[(f + 1) * 4 + 2];
            nw3 = wg[(f + 1) * 4 + 3];
            na  = *qp(tile, cols[f + 1], s);
        }
        float2 r01 = h2f(ca.x), r23 = h2f(ca.y);
        u64 d0 = pk2(r01.x, r01.x), d1 = pk2(r01.y, r01.y);
        u64 d2 = pk2(r23.x, r23.x), d3 = pk2(r23.y, r23.y);
        u64 u[8] = {cw0.x, cw0.y, cw1.x, cw1.y, cw2.x, cw2.y, cw3.x, cw3.y};
        #pragma unroll
        for (int op = 0; op < 8; op++) {
            acc[0][op] = fma2(d0, u[op], acc[0][op]);
            acc[1][op] = fma2(d1, u[op], acc[1][op]);
            acc[2][op] = fma2(d2, u[op], acc[2][op]);
            acc[3][op] = fma2(d3, u[op], acc[3][op]);
        }
        if (f < NF - 1) { cw0 = nw0; cw1 = nw1; cw2 = nw2; cw3 = nw3; ca = na; }
    }

    // tanh + fp16 writeback: 16 cols x 4 rows
    float v[4][NO];
    #pragma unroll
    for (int r = 0; r < 4; r++)
        #pragma unroll
        for (int op = 0; op < 8; op++)
            up2(acc[r][op], v[r][2 * op], v[r][2 * op + 1]);
    #pragma unroll
    for (int r = 0; r < 4; r++)
        #pragma unroll
        for (int o = 0; o < NO; o++)
            v[r][o] = tanhhw(v[r][o]);
    #pragma unroll
    for (int o = 0; o < NO; o++) {
        int c = colbase + g * NO + o;
        __half2 p0 = __floats2half2_rn(v[0][o], v[1][o]);
        __half2 p1 = __floats2half2_rn(v[2][o], v[3][o]);
        uint2 st;
        st.x = reinterpret_cast<unsigned&>(p0);
        st.y = reinterpret_cast<unsigned&>(p1);
        *qp(tile, c, s) = st;
    }
}

__global__ void __launch_bounds__(NTHR, 1)
model_kernel(const float* __restrict__ x,
             const float* __restrict__ W1, const float* __restrict__ b1,
             const float* __restrict__ W2, const float* __restrict__ b2,
             const float* __restrict__ W3, const float* __restrict__ b3,
             const float* __restrict__ Wo, const float* __restrict__ bo,
             const int* __restrict__ idx1, const int* __restrict__ idx2,
             const int* __restrict__ idx3, const int* __restrict__ idxo,
             float* __restrict__ out)
{
    extern __shared__ char smemraw[];
    uint2* tile = reinterpret_cast<uint2*>(smemraw);            // fp16 act tile
    float* wsm  = reinterpret_cast<float*>(smemraw + TILE_BYTES); // weight buf
    const int t = threadIdx.x;
    const int rowbase = blockIdx.x * RT;

    // ---- Stage x tile (16 rows x 512 cols) fp32->fp16 + W1 into SMEM ----
    {
        const float* xb = x + (size_t)rowbase * INC;
        #pragma unroll
        for (int k = 0; k < 8; k++) {
            int i  = t + k * NTHR;       // 0..2047
            int c  = i & 511;
            int qd = i >> 9;             // slot 0..3
            float r0 = __ldcs(&xb[(4 * qd + 0) * INC + c]);
            float r1 = __ldcs(&xb[(4 * qd + 1) * INC + c]);
            float r2 = __ldcs(&xb[(4 * qd + 2) * INC + c]);
            float r3 = __ldcs(&xb[(4 * qd + 3) * INC + c]);
            __half2 p0 = __floats2half2_rn(r0, r1);
            __half2 p1 = __floats2half2_rn(r2, r3);
            uint2 st;
            st.x = reinterpret_cast<unsigned&>(p0);
            st.y = reinterpret_cast<unsigned&>(p1);
            *qp(tile, c, qd) = st;
        }
        stageW(W1, wsm, t);
    }
    __syncthreads();

    const int g = t >> 2;   // group 0..63
    const int s = t & 3;    // row-quad 0..3

    glayer(tile, wsm, g, s, b1, idx1, 512);
    __syncthreads();
    stageW(W2, wsm, t);
    __syncthreads();
    glayer(tile, wsm, g, s, b2, idx2, 1536);
    __syncthreads();
    stageW(W3, wsm, t);
    __syncthreads();
    glayer(tile, wsm, g, s, b3, idx3, 2560);
    __syncthreads();

    // ---- Output layer: 4 groups x 48 f x 16 o, linear, fp32 out ----
    {
        int ot = t & 15;
        int og = (t >> 4) & 3;
        int so = t >> 6;                 // row-quad 0..3
        float bias = __ldg(&bo[og * 16 + ot]);
        u64 bd = pk2(bias, bias);
        u64 h01 = bd, h23 = bd;
        const int* gi = idxo + og * 48;
        const float* w = Wo + og * 48 * 16 + ot;
        #pragma unroll
        for (int f = 0; f < 48; f++) {
            int c = __ldg(&gi[f]);
            uint2 a = *qp(tile, c, so);
            float2 r01 = h2f(a.x), r23 = h2f(a.y);
            float wf = __ldg(&w[f * 16]);
            u64 wd = pk2(wf, wf);
            h01 = fma2(pk2(r01.x, r01.y), wd, h01);
            h23 = fma2(pk2(r23.x, r23.y), wd, h23);
        }
        float hv[4];
        up2(h01, hv[0], hv[1]);
        up2(h23, hv[2], hv[3]);
        float* ob = out + (size_t)(rowbase + 4 * so) * 64 + og * 16 + ot;
        ob[0]   = hv[0];
        ob[64]  = hv[1];
        ob[128] = hv[2];
        ob[192] = hv[3];
    }
}

extern "C" void kernel_launch(void* const* d_in, const int* in_sizes, int n_in,
                              void* d_out, int out_size)
{
    const float* x   = (const float*)d_in[0];
    const float* W1  = (const float*)d_in[1];
    const float* b1  = (const float*)d_in[2];
    const float* W2  = (const float*)d_in[3];
    const float* b2  = (const float*)d_in[4];
    const float* W3  = (const float*)d_in[5];
    const float* b3  = (const float*)d_in[6];
    const float* Wo  = (const float*)d_in[7];
    const float* bo  = (const float*)d_in[8];
    const int*   i1  = (const int*)d_in[9];
    const int*   i2  = (const int*)d_in[10];
    const int*   i3  = (const int*)d_in[11];
    const int*   io  = (const int*)d_in[12];
    float*       out = (float*)d_out;

    cudaFuncSetAttribute(model_kernel,
                         cudaFuncAttributeMaxDynamicSharedMemorySize, SMEM_ASK);
    model_kernel<<<NROWS / RT, NTHR, SMEM_ASK>>>(
        x, W1, b1, W2, b2, W3, b3, Wo, bo, i1, i2, i3, io, out);
}